// round 15
// baseline (speedup 1.0000x reference)
#include <cuda_runtime.h>
#include <cuda_bf16.h>
#include <math.h>
#include <stdint.h>

// Problem dims
#define Bc 4
#define Sc 2048
#define Dc 512
#define Hc 8
#define HDc 64
#define Fc 2048
#define Mc (Bc*Sc)   // 8192 rows

// ---------------- scratch (device globals) ---------------------------------
__device__ __nv_bfloat16 g_xb[(size_t)Mc * Dc];
__device__ __nv_bfloat16 g_qkv[(size_t)Mc * 3 * Dc];     // bf16 (q pre-scaled by 0.125*log2e)
__device__ __nv_bfloat16 g_attnb[(size_t)Mc * Dc];
__device__ float         g_proj[(size_t)Mc * Dc];
__device__ float         g_ln1[(size_t)Mc * Dc];
__device__ __nv_bfloat16 g_ln1b[(size_t)Mc * Dc];
__device__ __nv_bfloat16 g_hidb[(size_t)Mc * Fc];
__device__ float         g_ffn[(size_t)Mc * Dc];

#define WT_TOTAL 3145728
__device__ __nv_bfloat16 g_wb[WT_TOTAL];
#define OFF_WQKV 0
#define OFF_WO   786432
#define OFF_W1   1048576
#define OFF_W2   2097152

// epilogue flags
#define EPI_GELU    1
#define EPI_SCALEQ  2   // multiply cols < 512 by 0.125*log2e (softmax via exp2)

// ============================ helpers ======================================
__device__ __forceinline__ uint32_t smem_u32(const void* p) {
    uint32_t a;
    asm("{ .reg .u64 t; cvta.to.shared.u64 t, %1; cvt.u32.u64 %0, t; }" : "=r"(a) : "l"(p));
    return a;
}
__device__ __forceinline__ void ldsm_x4(uint32_t* r, uint32_t addr) {
    asm volatile("ldmatrix.sync.aligned.m8n8.x4.shared.b16 {%0,%1,%2,%3}, [%4];"
        : "=r"(r[0]), "=r"(r[1]), "=r"(r[2]), "=r"(r[3]) : "r"(addr));
}
__device__ __forceinline__ void ldsm_x4_t(uint32_t* r, uint32_t addr) {
    asm volatile("ldmatrix.sync.aligned.m8n8.x4.trans.shared.b16 {%0,%1,%2,%3}, [%4];"
        : "=r"(r[0]), "=r"(r[1]), "=r"(r[2]), "=r"(r[3]) : "r"(addr));
}
__device__ __forceinline__ void mma_bf16(float* d, const uint32_t* a, const uint32_t* b) {
    asm volatile("mma.sync.aligned.m16n8k16.row.col.f32.bf16.bf16.f32 "
        "{%0,%1,%2,%3}, {%4,%5,%6,%7}, {%8,%9}, {%0,%1,%2,%3};"
        : "+f"(d[0]), "+f"(d[1]), "+f"(d[2]), "+f"(d[3])
        : "r"(a[0]), "r"(a[1]), "r"(a[2]), "r"(a[3]), "r"(b[0]), "r"(b[1]));
}
__device__ __forceinline__ uint32_t packbf2(float x, float y) {
    __nv_bfloat162 t = __float22bfloat162_rn(make_float2(x, y));
    return *reinterpret_cast<uint32_t*>(&t);
}
__device__ __forceinline__ float ex2(float x) {
    float y;
    asm("ex2.approx.f32 %0, %1;" : "=f"(y) : "f"(x));
    return y;
}

// ======================= bf16 GEMM (single-pass, K-step 64) ================
#define BP 128
#define BSW(off) ((off) ^ (((off) >> 3) & 0x70))
#define BTILE_B (128 * BP)             // 16384 B
#define BSTAGE_B (2 * BTILE_B)         // 32768 B
#define BNS 3
#define BGEMM_SMEM (BNS * BSTAGE_B)    // 98304 B

__device__ __forceinline__ void cpb_stage(uint32_t st,
        const __nv_bfloat16* A, const __nv_bfloat16* B,
        int m0, int n0, int k0, int K, int tid)
{
#pragma unroll
    for (int t = 0; t < 4; t++) {
        int idx = tid + t * 256;
        int r = idx >> 3, c = idx & 7;
        uint32_t doff = BSW((uint32_t)(r * BP + c * 16));
        const void* asrc = A + (size_t)(m0 + r) * K + k0 + c * 8;
        const void* bsrc = B + (size_t)(n0 + r) * K + k0 + c * 8;
        asm volatile("cp.async.cg.shared.global [%0], [%1], 16;"
            :: "r"(st + doff), "l"(asrc) : "memory");
        asm volatile("cp.async.cg.shared.global [%0], [%1], 16;"
            :: "r"(st + BTILE_B + doff), "l"(bsrc) : "memory");
    }
}

__global__ __launch_bounds__(256, 2)
void gemm_bf16_kernel(const __nv_bfloat16* __restrict__ A, const __nv_bfloat16* __restrict__ B,
                      const float* __restrict__ bias, float* __restrict__ C,
                      __nv_bfloat16* __restrict__ Cb,
                      int K, int N, int flags)
{
    extern __shared__ char smem[];
    const uint32_t sbase = smem_u32(smem);
    const int tid = threadIdx.x;
    const int wid = tid >> 5;
    const int lane = tid & 31;
    const int wm = wid >> 2;
    const int wn = wid & 3;
    const int m0 = blockIdx.y << 7;
    const int n0 = blockIdx.x << 7;
    const int T = K >> 6;

    float acc[4][4][4];
#pragma unroll
    for (int i = 0; i < 4; i++)
#pragma unroll
        for (int j = 0; j < 4; j++)
#pragma unroll
            for (int k = 0; k < 4; k++) acc[i][j][k] = 0.0f;

    const uint32_t a_row = (uint32_t)(wm * 64 + (lane & 15));
    const uint32_t a_chk = (uint32_t)(lane >> 4);
    const uint32_t b_row = (uint32_t)(wn * 32 + (lane & 7) + ((lane >> 4) << 3));
    const uint32_t b_chk = (uint32_t)((lane >> 3) & 1);

#pragma unroll
    for (int s = 0; s < BNS - 1; s++) {
        if (s < T) cpb_stage(sbase + s * BSTAGE_B, A, B, m0, n0, s * 64, K, tid);
        asm volatile("cp.async.commit_group;" ::: "memory");
    }

    for (int kt = 0; kt < T; kt++) {
        asm volatile("cp.async.wait_group %0;" :: "n"(BNS - 2) : "memory");
        __syncthreads();

        const int pre = kt + BNS - 1;
        if (pre < T)
            cpb_stage(sbase + (pre % BNS) * BSTAGE_B, A, B, m0, n0, pre * 64, K, tid);
        asm volatile("cp.async.commit_group;" ::: "memory");

        const uint32_t stA = sbase + (kt % BNS) * BSTAGE_B;
        const uint32_t stB = stA + BTILE_B;
#pragma unroll
        for (int ks = 0; ks < 4; ks++) {
            uint32_t bf[2][4];
            const uint32_t akc = (uint32_t)(ks * 2) + a_chk;
            const uint32_t bkc = (uint32_t)(ks * 2) + b_chk;
#pragma unroll
            for (int bi = 0; bi < 2; bi++) {
                uint32_t bo = BSW((b_row + bi * 16) * BP + bkc * 16);
                ldsm_x4(bf[bi], stB + bo);
            }
#pragma unroll
            for (int mi = 0; mi < 4; mi++) {
                uint32_t af[4];
                uint32_t ao = BSW((a_row + mi * 16) * BP + akc * 16);
                ldsm_x4(af, stA + ao);
#pragma unroll
                for (int ni = 0; ni < 4; ni++)
                    mma_bf16(acc[mi][ni], af, &bf[ni >> 1][(ni & 1) * 2]);
            }
        }
    }

    const int row0 = m0 + wm * 64 + (lane >> 2);
    const int col0 = n0 + wn * 32 + (lane & 3) * 2;
#pragma unroll
    for (int mi = 0; mi < 4; mi++) {
#pragma unroll
        for (int ni = 0; ni < 4; ni++) {
            int col = col0 + ni * 8;
            float bx = __ldg(bias + col), by = __ldg(bias + col + 1);
            float qs = ((flags & EPI_SCALEQ) && col < 512) ? 0.18033688f : 1.0f;
#pragma unroll
            for (int half = 0; half < 2; half++) {
                int r = row0 + mi * 16 + half * 8;
                float vx = acc[mi][ni][half * 2 + 0] + bx;
                float vy = acc[mi][ni][half * 2 + 1] + by;
                if (flags & EPI_GELU) { vx *= normcdff(vx); vy *= normcdff(vy); }
                vx *= qs; vy *= qs;
                if (Cb)
                    *(uint32_t*)(Cb + (size_t)r * N + col) = packbf2(vx, vy);
                else
                    *(float2*)(C + (size_t)r * N + col) = make_float2(vx, vy);
            }
        }
    }
}

// ====================== flash attention (bf16, 3-stage KV pipeline) ========
#define FPITCH 144
#define FTILE (64 * FPITCH)                 // 9216 B
#define FQTILE (128 * FPITCH)               // 18432 B
#define FKVSET (2 * FTILE)                  // K + V per stage
#define FA_SMEM (FQTILE + 3 * FKVSET)       // 73728 B -> 2 CTAs/SM

__device__ __forceinline__ void fa_cp(uint32_t dst, const __nv_bfloat16* src) {
    asm volatile("cp.async.cg.shared.global [%0], [%1], 16;" :: "r"(dst), "l"(src) : "memory");
}

__device__ __forceinline__ void fa_load_kv(uint32_t st, const __nv_bfloat16* qkv,
                                           size_t brow0, int t, int h, int tid)
{
#pragma unroll
    for (int i = 0; i < 2; i++) {
        int idx = tid + i * 256;
        int r = idx >> 3, c = idx & 7;
        uint32_t d = (uint32_t)(r * FPITCH + c * 16);
        size_t base = (brow0 + t + r) * (size_t)(3 * Dc) + h * HDc + c * 8;
        fa_cp(st + 0 * FTILE + d, qkv + base + Dc);
        fa_cp(st + 1 * FTILE + d, qkv + base + 2 * Dc);
    }
}

__global__ __launch_bounds__(256, 2)
void flash_attn_mma_kernel(const __nv_bfloat16* __restrict__ qkv,
                           __nv_bfloat16* __restrict__ out)
{
    extern __shared__ char smem[];
    const uint32_t sb = smem_u32(smem);
    const uint32_t sQ = sb;
    const uint32_t sKV = sb + FQTILE;        // 3 stages

    const int tid = threadIdx.x;
    const int wid = tid >> 5, lane = tid & 31;
    const int bh = blockIdx.y;
    const int b = bh >> 3, h = bh & 7;
    const int q0 = blockIdx.x << 7;
    const size_t brow0 = (size_t)b * Sc;

    // group 0: Q + KV tile 0
#pragma unroll
    for (int i = 0; i < 4; i++) {
        int idx = tid + i * 256;
        int r = idx >> 3, c = idx & 7;
        uint32_t d = (uint32_t)(r * FPITCH + c * 16);
        size_t base = (brow0 + q0 + r) * (size_t)(3 * Dc) + h * HDc + c * 8;
        fa_cp(sQ + d, qkv + base);
    }
    fa_load_kv(sKV, qkv, brow0, 0, h, tid);
    asm volatile("cp.async.commit_group;" ::: "memory");
    // group 1: KV tile 1
    fa_load_kv(sKV + FKVSET, qkv, brow0, 64, h, tid);
    asm volatile("cp.async.commit_group;" ::: "memory");

    float l0 = 0.0f, l1 = 0.0f;
    float o[8][4];
#pragma unroll
    for (int j = 0; j < 8; j++)
#pragma unroll
        for (int k = 0; k < 4; k++) o[j][k] = 0.0f;

    const uint32_t a_row = (uint32_t)(wid * 16 + (lane & 15));
    const uint32_t a_chk = (uint32_t)(lane >> 4);
    const uint32_t b_row = (uint32_t)((lane & 7) + ((lane >> 4) << 3));
    const uint32_t b_chk = (uint32_t)((lane >> 3) & 1);
    const uint32_t v_row = (uint32_t)(lane & 15);
    const uint32_t v_col = (uint32_t)((lane >> 4) << 3);

    const int T = Sc / 64;
    for (int it = 0; it < T; it++) {
        // tile `it` guaranteed complete once <=1 group pending
        asm volatile("cp.async.wait_group 1;" ::: "memory");
        __syncthreads();     // also protects stage (it+2)%3 from overwrite

        const int pre = it + 2;
        if (pre < T)
            fa_load_kv(sKV + (uint32_t)(pre % 3) * FKVSET, qkv, brow0, pre * 64, h, tid);
        asm volatile("cp.async.commit_group;" ::: "memory");

        const uint32_t cur = sKV + (uint32_t)(it % 3) * FKVSET;

        // ---- S' = Q' K^T ----
        float sacc[8][4];
#pragma unroll
        for (int j = 0; j < 8; j++)
#pragma unroll
            for (int k = 0; k < 4; k++) sacc[j][k] = 0.0f;

#pragma unroll
        for (int ks = 0; ks < 4; ks++) {
            uint32_t qf[4];
            ldsm_x4(qf, sQ + a_row * FPITCH + (a_chk + 2 * ks) * 16);
#pragma unroll
            for (int nt = 0; nt < 4; nt++) {
                uint32_t kf[4];
                uint32_t bo = (b_row + nt * 16) * FPITCH + (b_chk + 2 * ks) * 16;
                ldsm_x4(kf, cur + bo);
                mma_bf16(sacc[2 * nt],     qf, kf);
                mma_bf16(sacc[2 * nt + 1], qf, kf + 2);
            }
        }

        // ---- interleaved exp2/pack + PV ----
#pragma unroll
        for (int ks = 0; ks < 4; ks++) {
            uint32_t ap[4];
            {
                float e0 = ex2(sacc[2 * ks][0]);
                float e1 = ex2(sacc[2 * ks][1]);
                float e2 = ex2(sacc[2 * ks][2]);
                float e3 = ex2(sacc[2 * ks][3]);
                l0 += e0 + e1; l1 += e2 + e3;
                ap[0] = packbf2(e0, e1);
                ap[1] = packbf2(e2, e3);
            }
            {
                float e0 = ex2(sacc[2 * ks + 1][0]);
                float e1 = ex2(sacc[2 * ks + 1][1]);
                float e2 = ex2(sacc[2 * ks + 1][2]);
                float e3 = ex2(sacc[2 * ks + 1][3]);
                l0 += e0 + e1; l1 += e2 + e3;
                ap[2] = packbf2(e0, e1);
                ap[3] = packbf2(e2, e3);
            }
#pragma unroll
            for (int nt = 0; nt < 4; nt++) {
                uint32_t vf[4];
                uint32_t vo = (ks * 16 + v_row) * FPITCH + (nt * 16 + v_col) * 2;
                ldsm_x4_t(vf, cur + FTILE + vo);
                mma_bf16(o[2 * nt],     ap, vf);
                mma_bf16(o[2 * nt + 1], ap, vf + 2);
            }
        }
    }

    l0 += __shfl_xor_sync(0xffffffffu, l0, 1);
    l0 += __shfl_xor_sync(0xffffffffu, l0, 2);
    l1 += __shfl_xor_sync(0xffffffffu, l1, 1);
    l1 += __shfl_xor_sync(0xffffffffu, l1, 2);

    const float inv0 = 1.0f / l0, inv1 = 1.0f / l1;
    const int r0 = (int)(brow0) + q0 + wid * 16 + (lane >> 2);
#pragma unroll
    for (int j = 0; j < 8; j++) {
        size_t col = (size_t)h * HDc + j * 8 + (lane & 3) * 2;
        *(uint32_t*)(out + (size_t)r0 * Dc + col) = packbf2(o[j][0] * inv0, o[j][1] * inv0);
        *(uint32_t*)(out + (size_t)(r0 + 8) * Dc + col) = packbf2(o[j][2] * inv1, o[j][3] * inv1);
    }
}

// =================== prep kernel (weights + x conversion, one launch) ======
__global__ __launch_bounds__(256)
void prep_kernel(const float* __restrict__ w_qkv, const float* __restrict__ w_o,
                 const float* __restrict__ w1, const float* __restrict__ w2,
                 const float* __restrict__ x,
                 __nv_bfloat16* __restrict__ Wb, __nv_bfloat16* __restrict__ xb)
{
    int id = blockIdx.x;
    if (id >= 3072) {
        // x -> bf16 (4096 blocks x 256 threads x 4 floats)
        int i = (id - 3072) * 256 + threadIdx.x;
        float4 v = ((const float4*)x)[i];
        ((uint32_t*)xb)[2 * i]     = packbf2(v.x, v.y);
        ((uint32_t*)xb)[2 * i + 1] = packbf2(v.z, v.w);
        return;
    }
    const float* W; int K, N, nx; size_t off;
    if (id < 768)        { W = w_qkv; K = Dc; N = 3 * Dc; nx = 48; off = OFF_WQKV; }
    else if (id < 1024)  { id -= 768;  W = w_o; K = Dc; N = Dc;    nx = 16; off = OFF_WO; }
    else if (id < 2048)  { id -= 1024; W = w1;  K = Dc; N = Fc;    nx = 64; off = OFF_W1; }
    else                 { id -= 2048; W = w2;  K = Fc; N = Dc;    nx = 16; off = OFF_W2; }
    const int n0 = (id % nx) * 32, k0 = (id / nx) * 32;

    __shared__ float tile[32][33];
    const int tx = threadIdx.x & 31, ty = threadIdx.x >> 5;
#pragma unroll
    for (int i = ty; i < 32; i += 8)
        tile[i][tx] = W[(size_t)(k0 + i) * N + n0 + tx];
    __syncthreads();
#pragma unroll
    for (int i = ty; i < 32; i += 8)
        Wb[off + (size_t)(n0 + i) * K + k0 + tx] = __float2bfloat16(tile[tx][i]);
}

// ======================= add + layernorm ===================================
__global__ __launch_bounds__(128)
void add_ln_kernel(const float* __restrict__ a, const float* __restrict__ r,
                   const float* __restrict__ g, const float* __restrict__ be,
                   float* __restrict__ out, __nv_bfloat16* __restrict__ out_b)
{
    const int row = blockIdx.x;
    const int tid = threadIdx.x;
    const float4 a4 = ((const float4*)(a + (size_t)row * Dc))[tid];
    const float4 r4 = ((const float4*)(r + (size_t)row * Dc))[tid];
    float v0 = a4.x + r4.x, v1 = a4.y + r4.y, v2 = a4.z + r4.z, v3 = a4.w + r4.w;

    float s = v0 + v1 + v2 + v3;
    float q = v0 * v0 + v1 * v1 + v2 * v2 + v3 * v3;
#pragma unroll
    for (int o = 16; o > 0; o >>= 1) {
        s += __shfl_xor_sync(0xffffffffu, s, o);
        q += __shfl_xor_sync(0xffffffffu, q, o);
    }
    __shared__ float ss[4], sq[4];
    if ((tid & 31) == 0) { ss[tid >> 5] = s; sq[tid >> 5] = q; }
    __syncthreads();
    s = ss[0] + ss[1] + ss[2] + ss[3];
    q = sq[0] + sq[1] + sq[2] + sq[3];

    const float mu = s * (1.0f / Dc);
    const float var = q * (1.0f / Dc) - mu * mu;
    const float rstd = rsqrtf(var + 1e-5f);

    const float4 g4 = ((const float4*)g)[tid];
    const float4 b4 = ((const float4*)be)[tid];
    float4 ov;
    ov.x = (v0 - mu) * rstd * g4.x + b4.x;
    ov.y = (v1 - mu) * rstd * g4.y + b4.y;
    ov.z = (v2 - mu) * rstd * g4.z + b4.z;
    ov.w = (v3 - mu) * rstd * g4.w + b4.w;
    if (out) ((float4*)(out + (size_t)row * Dc))[tid] = ov;
    if (out_b) {
        uint32_t* bp = (uint32_t*)(out_b + (size_t)row * Dc) + 2 * tid;
        bp[0] = packbf2(ov.x, ov.y);
        bp[1] = packbf2(ov.z, ov.w);
    }
}

// ---------------------------------------------------------------------------
extern "C" void kernel_launch(void* const* d_in, const int* in_sizes, int n_in,
                              void* d_out, int out_size)
{
    (void)in_sizes; (void)n_in; (void)out_size;
    const float* x     = (const float*)d_in[0];
    const float* w_qkv = (const float*)d_in[1];
    const float* b_qkv = (const float*)d_in[2];
    const float* w_o   = (const float*)d_in[3];
    const float* b_o   = (const float*)d_in[4];
    const float* w1    = (const float*)d_in[5];
    const float* b1    = (const float*)d_in[6];
    const float* w2    = (const float*)d_in[7];
    const float* b2    = (const float*)d_in[8];
    const float* g1    = (const float*)d_in[9];
    const float* be1   = (const float*)d_in[10];
    const float* g2    = (const float*)d_in[11];
    const float* be2   = (const float*)d_in[12];

    float *proj, *ln1, *ffn;
    __nv_bfloat16 *xb, *qkv, *attnb, *ln1b, *hidb, *wb;
    cudaGetSymbolAddress((void**)&xb,    g_xb);
    cudaGetSymbolAddress((void**)&qkv,   g_qkv);
    cudaGetSymbolAddress((void**)&attnb, g_attnb);
    cudaGetSymbolAddress((void**)&proj,  g_proj);
    cudaGetSymbolAddress((void**)&ln1,   g_ln1);
    cudaGetSymbolAddress((void**)&ln1b,  g_ln1b);
    cudaGetSymbolAddress((void**)&hidb,  g_hidb);
    cudaGetSymbolAddress((void**)&ffn,   g_ffn);
    cudaGetSymbolAddress((void**)&wb,    g_wb);

    cudaFuncSetAttribute(gemm_bf16_kernel,
                         cudaFuncAttributeMaxDynamicSharedMemorySize, BGEMM_SMEM);
    cudaFuncSetAttribute(flash_attn_mma_kernel,
                         cudaFuncAttributeMaxDynamicSharedMemorySize, FA_SMEM);

    // weights transpose + x conversion, one launch
    prep_kernel<<<3072 + 4096, 256>>>(w_qkv, w_o, w1, w2, x, wb, xb);

    // 1) qkv = xb @ w_qkvb + b_qkv (bf16 out, q scaled 0.125*log2e)
    gemm_bf16_kernel<<<dim3(12, 64), 256, BGEMM_SMEM>>>(xb, wb + OFF_WQKV, b_qkv,
                                                        nullptr, qkv, Dc, 3 * Dc, EPI_SCALEQ);
    // 2) attention (bf16 -> bf16)
    flash_attn_mma_kernel<<<dim3(Sc / 128, Bc * Hc), 256, FA_SMEM>>>(qkv, attnb);
    // 3) proj = attnb @ w_ob + b_o (fp32 out)
    gemm_bf16_kernel<<<dim3(4, 64), 256, BGEMM_SMEM>>>(attnb, wb + OFF_WO, b_o,
                                                       proj, nullptr, Dc, Dc, 0);
    // 4) ln1 = layernorm(proj + x)
    add_ln_kernel<<<Mc, 128>>>(proj, x, g1, be1, ln1, ln1b);
    // 5) hid = gelu(ln1b @ w1b + b1)
    gemm_bf16_kernel<<<dim3(16, 64), 256, BGEMM_SMEM>>>(ln1b, wb + OFF_W1, b1,
                                                        nullptr, hidb, Dc, Fc, EPI_GELU);
    // 6) ffn = hidb @ w2b + b2
    gemm_bf16_kernel<<<dim3(4, 64), 256, BGEMM_SMEM>>>(hidb, wb + OFF_W2, b2,
                                                       ffn, nullptr, Fc, Dc, 0);
    // 7) out = layernorm(ffn + ln1)
    add_ln_kernel<<<Mc, 128>>>(ffn, ln1, g2, be2, (float*)d_out, nullptr);
}

// round 16
// speedup vs baseline: 1.0327x; 1.0327x over previous
#include <cuda_runtime.h>
#include <cuda_bf16.h>
#include <math.h>
#include <stdint.h>

// Problem dims
#define Bc 4
#define Sc 2048
#define Dc 512
#define Hc 8
#define HDc 64
#define Fc 2048
#define Mc (Bc*Sc)   // 8192 rows

// ---------------- scratch (device globals) ---------------------------------
__device__ __nv_bfloat16 g_xb[(size_t)Mc * Dc];
__device__ __nv_bfloat16 g_qkv[(size_t)Mc * 3 * Dc];     // bf16 (q pre-scaled by 0.125*log2e)
__device__ __nv_bfloat16 g_attnb[(size_t)Mc * Dc];
__device__ float         g_proj[(size_t)Mc * Dc];
__device__ float         g_ln1[(size_t)Mc * Dc];
__device__ __nv_bfloat16 g_ln1b[(size_t)Mc * Dc];
__device__ __nv_bfloat16 g_hidb[(size_t)Mc * Fc];
__device__ float         g_ffn[(size_t)Mc * Dc];

#define WT_TOTAL 3145728
__device__ __nv_bfloat16 g_wb[WT_TOTAL];
#define OFF_WQKV 0
#define OFF_WO   786432
#define OFF_W1   1048576
#define OFF_W2   2097152

// epilogue flags
#define EPI_GELU    1
#define EPI_SCALEQ  2   // multiply cols < 512 by 0.125*log2e (softmax via exp2)

// ============================ helpers ======================================
__device__ __forceinline__ uint32_t smem_u32(const void* p) {
    uint32_t a;
    asm("{ .reg .u64 t; cvta.to.shared.u64 t, %1; cvt.u32.u64 %0, t; }" : "=r"(a) : "l"(p));
    return a;
}
__device__ __forceinline__ void ldsm_x4(uint32_t* r, uint32_t addr) {
    asm volatile("ldmatrix.sync.aligned.m8n8.x4.shared.b16 {%0,%1,%2,%3}, [%4];"
        : "=r"(r[0]), "=r"(r[1]), "=r"(r[2]), "=r"(r[3]) : "r"(addr));
}
__device__ __forceinline__ void ldsm_x4_t(uint32_t* r, uint32_t addr) {
    asm volatile("ldmatrix.sync.aligned.m8n8.x4.trans.shared.b16 {%0,%1,%2,%3}, [%4];"
        : "=r"(r[0]), "=r"(r[1]), "=r"(r[2]), "=r"(r[3]) : "r"(addr));
}
__device__ __forceinline__ void mma_bf16(float* d, const uint32_t* a, const uint32_t* b) {
    asm volatile("mma.sync.aligned.m16n8k16.row.col.f32.bf16.bf16.f32 "
        "{%0,%1,%2,%3}, {%4,%5,%6,%7}, {%8,%9}, {%0,%1,%2,%3};"
        : "+f"(d[0]), "+f"(d[1]), "+f"(d[2]), "+f"(d[3])
        : "r"(a[0]), "r"(a[1]), "r"(a[2]), "r"(a[3]), "r"(b[0]), "r"(b[1]));
}
__device__ __forceinline__ uint32_t packbf2(float x, float y) {
    __nv_bfloat162 t = __float22bfloat162_rn(make_float2(x, y));
    return *reinterpret_cast<uint32_t*>(&t);
}
__device__ __forceinline__ float ex2(float x) {
    float y;
    asm("ex2.approx.f32 %0, %1;" : "=f"(y) : "f"(x));
    return y;
}

// ======================= bf16 GEMM (single-pass, K-step 64) ================
#define BP 128
#define BSW(off) ((off) ^ (((off) >> 3) & 0x70))
#define BTILE_B (128 * BP)             // 16384 B
#define BSTAGE_B (2 * BTILE_B)         // 32768 B
#define BNS 3
#define BGEMM_SMEM (BNS * BSTAGE_B)    // 98304 B

__device__ __forceinline__ void cpb_stage(uint32_t st,
        const __nv_bfloat16* A, const __nv_bfloat16* B,
        int m0, int n0, int k0, int K, int tid)
{
#pragma unroll
    for (int t = 0; t < 4; t++) {
        int idx = tid + t * 256;
        int r = idx >> 3, c = idx & 7;
        uint32_t doff = BSW((uint32_t)(r * BP + c * 16));
        const void* asrc = A + (size_t)(m0 + r) * K + k0 + c * 8;
        const void* bsrc = B + (size_t)(n0 + r) * K + k0 + c * 8;
        asm volatile("cp.async.cg.shared.global [%0], [%1], 16;"
            :: "r"(st + doff), "l"(asrc) : "memory");
        asm volatile("cp.async.cg.shared.global [%0], [%1], 16;"
            :: "r"(st + BTILE_B + doff), "l"(bsrc) : "memory");
    }
}

__global__ __launch_bounds__(256, 2)
void gemm_bf16_kernel(const __nv_bfloat16* __restrict__ A, const __nv_bfloat16* __restrict__ B,
                      const float* __restrict__ bias, float* __restrict__ C,
                      __nv_bfloat16* __restrict__ Cb,
                      int K, int N, int flags)
{
    extern __shared__ char smem[];
    const uint32_t sbase = smem_u32(smem);
    const int tid = threadIdx.x;
    const int wid = tid >> 5;
    const int lane = tid & 31;
    const int wm = wid >> 2;
    const int wn = wid & 3;
    const int m0 = blockIdx.y << 7;
    const int n0 = blockIdx.x << 7;
    const int T = K >> 6;

    float acc[4][4][4];
#pragma unroll
    for (int i = 0; i < 4; i++)
#pragma unroll
        for (int j = 0; j < 4; j++)
#pragma unroll
            for (int k = 0; k < 4; k++) acc[i][j][k] = 0.0f;

    const uint32_t a_row = (uint32_t)(wm * 64 + (lane & 15));
    const uint32_t a_chk = (uint32_t)(lane >> 4);
    const uint32_t b_row = (uint32_t)(wn * 32 + (lane & 7) + ((lane >> 4) << 3));
    const uint32_t b_chk = (uint32_t)((lane >> 3) & 1);

#pragma unroll
    for (int s = 0; s < BNS - 1; s++) {
        if (s < T) cpb_stage(sbase + s * BSTAGE_B, A, B, m0, n0, s * 64, K, tid);
        asm volatile("cp.async.commit_group;" ::: "memory");
    }

    for (int kt = 0; kt < T; kt++) {
        asm volatile("cp.async.wait_group %0;" :: "n"(BNS - 2) : "memory");
        __syncthreads();

        const int pre = kt + BNS - 1;
        if (pre < T)
            cpb_stage(sbase + (pre % BNS) * BSTAGE_B, A, B, m0, n0, pre * 64, K, tid);
        asm volatile("cp.async.commit_group;" ::: "memory");

        const uint32_t stA = sbase + (kt % BNS) * BSTAGE_B;
        const uint32_t stB = stA + BTILE_B;
#pragma unroll
        for (int ks = 0; ks < 4; ks++) {
            uint32_t bf[2][4];
            const uint32_t akc = (uint32_t)(ks * 2) + a_chk;
            const uint32_t bkc = (uint32_t)(ks * 2) + b_chk;
#pragma unroll
            for (int bi = 0; bi < 2; bi++) {
                uint32_t bo = BSW((b_row + bi * 16) * BP + bkc * 16);
                ldsm_x4(bf[bi], stB + bo);
            }
#pragma unroll
            for (int mi = 0; mi < 4; mi++) {
                uint32_t af[4];
                uint32_t ao = BSW((a_row + mi * 16) * BP + akc * 16);
                ldsm_x4(af, stA + ao);
#pragma unroll
                for (int ni = 0; ni < 4; ni++)
                    mma_bf16(acc[mi][ni], af, &bf[ni >> 1][(ni & 1) * 2]);
            }
        }
    }

    const int row0 = m0 + wm * 64 + (lane >> 2);
    const int col0 = n0 + wn * 32 + (lane & 3) * 2;
#pragma unroll
    for (int mi = 0; mi < 4; mi++) {
#pragma unroll
        for (int ni = 0; ni < 4; ni++) {
            int col = col0 + ni * 8;
            float bx = __ldg(bias + col), by = __ldg(bias + col + 1);
            float qs = ((flags & EPI_SCALEQ) && col < 512) ? 0.18033688f : 1.0f;
#pragma unroll
            for (int half = 0; half < 2; half++) {
                int r = row0 + mi * 16 + half * 8;
                float vx = acc[mi][ni][half * 2 + 0] + bx;
                float vy = acc[mi][ni][half * 2 + 1] + by;
                if (flags & EPI_GELU) { vx *= normcdff(vx); vy *= normcdff(vy); }
                vx *= qs; vy *= qs;
                if (Cb)
                    *(uint32_t*)(Cb + (size_t)r * N + col) = packbf2(vx, vy);
                else
                    *(float2*)(C + (size_t)r * N + col) = make_float2(vx, vy);
            }
        }
    }
}

// ====================== flash attention (bf16, 2-stage, Q hoisted) =========
#define FPITCH 144
#define FTILE (64 * FPITCH)
#define FQTILE (128 * FPITCH)
#define FA_SMEM (FQTILE + 4 * FTILE)        // 55296 B

__device__ __forceinline__ void fa_cp(uint32_t dst, const __nv_bfloat16* src) {
    asm volatile("cp.async.cg.shared.global [%0], [%1], 16;" :: "r"(dst), "l"(src) : "memory");
}

__device__ __forceinline__ void fa_load_kv(uint32_t st, const __nv_bfloat16* qkv,
                                           size_t brow0, int t, int h, int tid)
{
#pragma unroll
    for (int i = 0; i < 2; i++) {
        int idx = tid + i * 256;
        int r = idx >> 3, c = idx & 7;
        uint32_t d = (uint32_t)(r * FPITCH + c * 16);
        size_t base = (brow0 + t + r) * (size_t)(3 * Dc) + h * HDc + c * 8;
        fa_cp(st + 0 * FTILE + d, qkv + base + Dc);
        fa_cp(st + 1 * FTILE + d, qkv + base + 2 * Dc);
    }
}

__global__ __launch_bounds__(256, 2)
void flash_attn_mma_kernel(const __nv_bfloat16* __restrict__ qkv,
                           __nv_bfloat16* __restrict__ out)
{
    extern __shared__ char smem[];
    const uint32_t sb = smem_u32(smem);
    const uint32_t sQ = sb;
    const uint32_t sKV = sb + FQTILE;

    const int tid = threadIdx.x;
    const int wid = tid >> 5, lane = tid & 31;
    const int bh = blockIdx.y;
    const int b = bh >> 3, h = bh & 7;
    const int q0 = blockIdx.x << 7;
    const size_t brow0 = (size_t)b * Sc;

#pragma unroll
    for (int i = 0; i < 4; i++) {
        int idx = tid + i * 256;
        int r = idx >> 3, c = idx & 7;
        uint32_t d = (uint32_t)(r * FPITCH + c * 16);
        size_t base = (brow0 + q0 + r) * (size_t)(3 * Dc) + h * HDc + c * 8;
        fa_cp(sQ + d, qkv + base);
    }
    fa_load_kv(sKV, qkv, brow0, 0, h, tid);
    asm volatile("cp.async.commit_group;" ::: "memory");
    asm volatile("cp.async.wait_group 0;" ::: "memory");
    __syncthreads();

    const uint32_t a_row = (uint32_t)(wid * 16 + (lane & 15));
    const uint32_t a_chk = (uint32_t)(lane >> 4);
    const uint32_t b_row = (uint32_t)((lane & 7) + ((lane >> 4) << 3));
    const uint32_t b_chk = (uint32_t)((lane >> 3) & 1);
    const uint32_t v_row = (uint32_t)(lane & 15);
    const uint32_t v_col = (uint32_t)((lane >> 4) << 3);

    // ---- hoist loop-invariant Q fragments (saves 4 ldsm per iteration) ----
    uint32_t qreg[4][4];
#pragma unroll
    for (int ks = 0; ks < 4; ks++)
        ldsm_x4(qreg[ks], sQ + a_row * FPITCH + (a_chk + 2 * ks) * 16);

    float l0 = 0.0f, l1 = 0.0f;
    float o[8][4];
#pragma unroll
    for (int j = 0; j < 8; j++)
#pragma unroll
        for (int k = 0; k < 4; k++) o[j][k] = 0.0f;

    const int T = Sc / 64;
    for (int it = 0; it < T; it++) {
        const uint32_t cur = sKV + (uint32_t)(it & 1) * (2 * FTILE);
        if (it + 1 < T)
            fa_load_kv(sKV + (uint32_t)((it + 1) & 1) * (2 * FTILE),
                       qkv, brow0, (it + 1) * 64, h, tid);
        asm volatile("cp.async.commit_group;" ::: "memory");

        // ---- S' = Q' K^T ----
        float sacc[8][4];
#pragma unroll
        for (int j = 0; j < 8; j++)
#pragma unroll
            for (int k = 0; k < 4; k++) sacc[j][k] = 0.0f;

#pragma unroll
        for (int ks = 0; ks < 4; ks++) {
#pragma unroll
            for (int nt = 0; nt < 4; nt++) {
                uint32_t kf[4];
                uint32_t bo = (b_row + nt * 16) * FPITCH + (b_chk + 2 * ks) * 16;
                ldsm_x4(kf, cur + bo);
                mma_bf16(sacc[2 * nt],     qreg[ks], kf);
                mma_bf16(sacc[2 * nt + 1], qreg[ks], kf + 2);
            }
        }

        // ---- interleaved exp2/pack + PV ----
#pragma unroll
        for (int ks = 0; ks < 4; ks++) {
            uint32_t ap[4];
            {
                float e0 = ex2(sacc[2 * ks][0]);
                float e1 = ex2(sacc[2 * ks][1]);
                float e2 = ex2(sacc[2 * ks][2]);
                float e3 = ex2(sacc[2 * ks][3]);
                l0 += e0 + e1; l1 += e2 + e3;
                ap[0] = packbf2(e0, e1);
                ap[1] = packbf2(e2, e3);
            }
            {
                float e0 = ex2(sacc[2 * ks + 1][0]);
                float e1 = ex2(sacc[2 * ks + 1][1]);
                float e2 = ex2(sacc[2 * ks + 1][2]);
                float e3 = ex2(sacc[2 * ks + 1][3]);
                l0 += e0 + e1; l1 += e2 + e3;
                ap[2] = packbf2(e0, e1);
                ap[3] = packbf2(e2, e3);
            }
#pragma unroll
            for (int nt = 0; nt < 4; nt++) {
                uint32_t vf[4];
                uint32_t vo = (ks * 16 + v_row) * FPITCH + (nt * 16 + v_col) * 2;
                ldsm_x4_t(vf, cur + FTILE + vo);
                mma_bf16(o[2 * nt],     ap, vf);
                mma_bf16(o[2 * nt + 1], ap, vf + 2);
            }
        }

        if (it + 1 < T) asm volatile("cp.async.wait_group 0;" ::: "memory");
        __syncthreads();
    }

    l0 += __shfl_xor_sync(0xffffffffu, l0, 1);
    l0 += __shfl_xor_sync(0xffffffffu, l0, 2);
    l1 += __shfl_xor_sync(0xffffffffu, l1, 1);
    l1 += __shfl_xor_sync(0xffffffffu, l1, 2);

    const float inv0 = 1.0f / l0, inv1 = 1.0f / l1;
    const int r0 = (int)(brow0) + q0 + wid * 16 + (lane >> 2);
#pragma unroll
    for (int j = 0; j < 8; j++) {
        size_t col = (size_t)h * HDc + j * 8 + (lane & 3) * 2;
        *(uint32_t*)(out + (size_t)r0 * Dc + col) = packbf2(o[j][0] * inv0, o[j][1] * inv0);
        *(uint32_t*)(out + (size_t)(r0 + 8) * Dc + col) = packbf2(o[j][2] * inv1, o[j][3] * inv1);
    }
}

// =================== prep kernel (weights + x conversion, one launch) ======
__global__ __launch_bounds__(256)
void prep_kernel(const float* __restrict__ w_qkv, const float* __restrict__ w_o,
                 const float* __restrict__ w1, const float* __restrict__ w2,
                 const float* __restrict__ x,
                 __nv_bfloat16* __restrict__ Wb, __nv_bfloat16* __restrict__ xb)
{
    int id = blockIdx.x;
    if (id >= 3072) {
        int i = (id - 3072) * 256 + threadIdx.x;
        float4 v = ((const float4*)x)[i];
        ((uint32_t*)xb)[2 * i]     = packbf2(v.x, v.y);
        ((uint32_t*)xb)[2 * i + 1] = packbf2(v.z, v.w);
        return;
    }
    const float* W; int K, N, nx; size_t off;
    if (id < 768)        { W = w_qkv; K = Dc; N = 3 * Dc; nx = 48; off = OFF_WQKV; }
    else if (id < 1024)  { id -= 768;  W = w_o; K = Dc; N = Dc;    nx = 16; off = OFF_WO; }
    else if (id < 2048)  { id -= 1024; W = w1;  K = Dc; N = Fc;    nx = 64; off = OFF_W1; }
    else                 { id -= 2048; W = w2;  K = Fc; N = Dc;    nx = 16; off = OFF_W2; }
    const int n0 = (id % nx) * 32, k0 = (id / nx) * 32;

    __shared__ float tile[32][33];
    const int tx = threadIdx.x & 31, ty = threadIdx.x >> 5;
#pragma unroll
    for (int i = ty; i < 32; i += 8)
        tile[i][tx] = W[(size_t)(k0 + i) * N + n0 + tx];
    __syncthreads();
#pragma unroll
    for (int i = ty; i < 32; i += 8)
        Wb[off + (size_t)(n0 + i) * K + k0 + tx] = __float2bfloat16(tile[tx][i]);
}

// ======================= add + layernorm ===================================
__global__ __launch_bounds__(128)
void add_ln_kernel(const float* __restrict__ a, const float* __restrict__ r,
                   const float* __restrict__ g, const float* __restrict__ be,
                   float* __restrict__ out, __nv_bfloat16* __restrict__ out_b)
{
    const int row = blockIdx.x;
    const int tid = threadIdx.x;
    const float4 a4 = ((const float4*)(a + (size_t)row * Dc))[tid];
    const float4 r4 = ((const float4*)(r + (size_t)row * Dc))[tid];
    float v0 = a4.x + r4.x, v1 = a4.y + r4.y, v2 = a4.z + r4.z, v3 = a4.w + r4.w;

    float s = v0 + v1 + v2 + v3;
    float q = v0 * v0 + v1 * v1 + v2 * v2 + v3 * v3;
#pragma unroll
    for (int o = 16; o > 0; o >>= 1) {
        s += __shfl_xor_sync(0xffffffffu, s, o);
        q += __shfl_xor_sync(0xffffffffu, q, o);
    }
    __shared__ float ss[4], sq[4];
    if ((tid & 31) == 0) { ss[tid >> 5] = s; sq[tid >> 5] = q; }
    __syncthreads();
    s = ss[0] + ss[1] + ss[2] + ss[3];
    q = sq[0] + sq[1] + sq[2] + sq[3];

    const float mu = s * (1.0f / Dc);
    const float var = q * (1.0f / Dc) - mu * mu;
    const float rstd = rsqrtf(var + 1e-5f);

    const float4 g4 = ((const float4*)g)[tid];
    const float4 b4 = ((const float4*)be)[tid];
    float4 ov;
    ov.x = (v0 - mu) * rstd * g4.x + b4.x;
    ov.y = (v1 - mu) * rstd * g4.y + b4.y;
    ov.z = (v2 - mu) * rstd * g4.z + b4.z;
    ov.w = (v3 - mu) * rstd * g4.w + b4.w;
    if (out) ((float4*)(out + (size_t)row * Dc))[tid] = ov;
    if (out_b) {
        uint32_t* bp = (uint32_t*)(out_b + (size_t)row * Dc) + 2 * tid;
        bp[0] = packbf2(ov.x, ov.y);
        bp[1] = packbf2(ov.z, ov.w);
    }
}

// ---------------------------------------------------------------------------
extern "C" void kernel_launch(void* const* d_in, const int* in_sizes, int n_in,
                              void* d_out, int out_size)
{
    (void)in_sizes; (void)n_in; (void)out_size;
    const float* x     = (const float*)d_in[0];
    const float* w_qkv = (const float*)d_in[1];
    const float* b_qkv = (const float*)d_in[2];
    const float* w_o   = (const float*)d_in[3];
    const float* b_o   = (const float*)d_in[4];
    const float* w1    = (const float*)d_in[5];
    const float* b1    = (const float*)d_in[6];
    const float* w2    = (const float*)d_in[7];
    const float* b2    = (const float*)d_in[8];
    const float* g1    = (const float*)d_in[9];
    const float* be1   = (const float*)d_in[10];
    const float* g2    = (const float*)d_in[11];
    const float* be2   = (const float*)d_in[12];

    float *proj, *ln1, *ffn;
    __nv_bfloat16 *xb, *qkv, *attnb, *ln1b, *hidb, *wb;
    cudaGetSymbolAddress((void**)&xb,    g_xb);
    cudaGetSymbolAddress((void**)&qkv,   g_qkv);
    cudaGetSymbolAddress((void**)&attnb, g_attnb);
    cudaGetSymbolAddress((void**)&proj,  g_proj);
    cudaGetSymbolAddress((void**)&ln1,   g_ln1);
    cudaGetSymbolAddress((void**)&ln1b,  g_ln1b);
    cudaGetSymbolAddress((void**)&hidb,  g_hidb);
    cudaGetSymbolAddress((void**)&ffn,   g_ffn);
    cudaGetSymbolAddress((void**)&wb,    g_wb);

    cudaFuncSetAttribute(gemm_bf16_kernel,
                         cudaFuncAttributeMaxDynamicSharedMemorySize, BGEMM_SMEM);
    cudaFuncSetAttribute(flash_attn_mma_kernel,
                         cudaFuncAttributeMaxDynamicSharedMemorySize, FA_SMEM);

    prep_kernel<<<3072 + 4096, 256>>>(w_qkv, w_o, w1, w2, x, wb, xb);

    gemm_bf16_kernel<<<dim3(12, 64), 256, BGEMM_SMEM>>>(xb, wb + OFF_WQKV, b_qkv,
                                                        nullptr, qkv, Dc, 3 * Dc, EPI_SCALEQ);
    flash_attn_mma_kernel<<<dim3(Sc / 128, Bc * Hc), 256, FA_SMEM>>>(qkv, attnb);
    gemm_bf16_kernel<<<dim3(4, 64), 256, BGEMM_SMEM>>>(attnb, wb + OFF_WO, b_o,
                                                       proj, nullptr, Dc, Dc, 0);
    add_ln_kernel<<<Mc, 128>>>(proj, x, g1, be1, ln1, ln1b);
    gemm_bf16_kernel<<<dim3(16, 64), 256, BGEMM_SMEM>>>(ln1b, wb + OFF_W1, b1,
                                                        nullptr, hidb, Dc, Fc, EPI_GELU);
    gemm_bf16_kernel<<<dim3(4, 64), 256, BGEMM_SMEM>>>(hidb, wb + OFF_W2, b2,
                                                       ffn, nullptr, Fc, Dc, 0);
    add_ln_kernel<<<Mc, 128>>>(ffn, ln1, g2, be2, (float*)d_out, nullptr);
}

// round 17
// speedup vs baseline: 1.0381x; 1.0052x over previous
#include <cuda_runtime.h>
#include <cuda_bf16.h>
#include <math.h>
#include <stdint.h>

// Problem dims
#define Bc 4
#define Sc 2048
#define Dc 512
#define Hc 8
#define HDc 64
#define Fc 2048
#define Mc (Bc*Sc)   // 8192 rows

// ---------------- scratch (device globals) ---------------------------------
__device__ __nv_bfloat16 g_xb[(size_t)Mc * Dc];
__device__ __nv_bfloat16 g_qkv[(size_t)Mc * 3 * Dc];     // bf16 (q pre-scaled by 0.125*log2e)
__device__ __nv_bfloat16 g_attnb[(size_t)Mc * Dc];
__device__ float         g_proj[(size_t)Mc * Dc];
__device__ float         g_ln1[(size_t)Mc * Dc];
__device__ __nv_bfloat16 g_ln1b[(size_t)Mc * Dc];
__device__ __nv_bfloat16 g_hidb[(size_t)Mc * Fc];
__device__ float         g_ffn[(size_t)Mc * Dc];

#define WT_TOTAL 3145728
__device__ __nv_bfloat16 g_wb[WT_TOTAL];
#define OFF_WQKV 0
#define OFF_WO   786432
#define OFF_W1   1048576
#define OFF_W2   2097152

// epilogue flags
#define EPI_GELU    1
#define EPI_SCALEQ  2   // multiply cols < 512 by 0.125*log2e (softmax via exp2)

// ============================ helpers ======================================
__device__ __forceinline__ uint32_t smem_u32(const void* p) {
    uint32_t a;
    asm("{ .reg .u64 t; cvta.to.shared.u64 t, %1; cvt.u32.u64 %0, t; }" : "=r"(a) : "l"(p));
    return a;
}
__device__ __forceinline__ void ldsm_x4(uint32_t* r, uint32_t addr) {
    asm volatile("ldmatrix.sync.aligned.m8n8.x4.shared.b16 {%0,%1,%2,%3}, [%4];"
        : "=r"(r[0]), "=r"(r[1]), "=r"(r[2]), "=r"(r[3]) : "r"(addr));
}
__device__ __forceinline__ void ldsm_x4_t(uint32_t* r, uint32_t addr) {
    asm volatile("ldmatrix.sync.aligned.m8n8.x4.trans.shared.b16 {%0,%1,%2,%3}, [%4];"
        : "=r"(r[0]), "=r"(r[1]), "=r"(r[2]), "=r"(r[3]) : "r"(addr));
}
__device__ __forceinline__ void mma_bf16(float* d, const uint32_t* a, const uint32_t* b) {
    asm volatile("mma.sync.aligned.m16n8k16.row.col.f32.bf16.bf16.f32 "
        "{%0,%1,%2,%3}, {%4,%5,%6,%7}, {%8,%9}, {%0,%1,%2,%3};"
        : "+f"(d[0]), "+f"(d[1]), "+f"(d[2]), "+f"(d[3])
        : "r"(a[0]), "r"(a[1]), "r"(a[2]), "r"(a[3]), "r"(b[0]), "r"(b[1]));
}
__device__ __forceinline__ uint32_t packbf2(float x, float y) {
    __nv_bfloat162 t = __float22bfloat162_rn(make_float2(x, y));
    return *reinterpret_cast<uint32_t*>(&t);
}
__device__ __forceinline__ float ex2(float x) {
    float y;
    asm("ex2.approx.f32 %0, %1;" : "=f"(y) : "f"(x));
    return y;
}

// ======================= bf16 GEMM (single-pass, K-step 64) ================
#define BP 128
#define BSW(off) ((off) ^ (((off) >> 3) & 0x70))
#define BTILE_B (128 * BP)             // 16384 B
#define BSTAGE_B (2 * BTILE_B)         // 32768 B
#define BNS 3
#define BGEMM_SMEM (BNS * BSTAGE_B)    // 98304 B

__device__ __forceinline__ void cpb_stage(uint32_t st,
        const __nv_bfloat16* A, const __nv_bfloat16* B,
        int m0, int n0, int k0, int K, int tid)
{
#pragma unroll
    for (int t = 0; t < 4; t++) {
        int idx = tid + t * 256;
        int r = idx >> 3, c = idx & 7;
        uint32_t doff = BSW((uint32_t)(r * BP + c * 16));
        const void* asrc = A + (size_t)(m0 + r) * K + k0 + c * 8;
        const void* bsrc = B + (size_t)(n0 + r) * K + k0 + c * 8;
        asm volatile("cp.async.cg.shared.global [%0], [%1], 16;"
            :: "r"(st + doff), "l"(asrc) : "memory");
        asm volatile("cp.async.cg.shared.global [%0], [%1], 16;"
            :: "r"(st + BTILE_B + doff), "l"(bsrc) : "memory");
    }
}

__global__ __launch_bounds__(256, 2)
void gemm_bf16_kernel(const __nv_bfloat16* __restrict__ A, const __nv_bfloat16* __restrict__ B,
                      const float* __restrict__ bias, float* __restrict__ C,
                      __nv_bfloat16* __restrict__ Cb,
                      int K, int N, int flags)
{
    extern __shared__ char smem[];
    const uint32_t sbase = smem_u32(smem);
    const int tid = threadIdx.x;
    const int wid = tid >> 5;
    const int lane = tid & 31;
    const int wm = wid >> 2;
    const int wn = wid & 3;
    const int m0 = blockIdx.y << 7;
    const int n0 = blockIdx.x << 7;
    const int T = K >> 6;

    float acc[4][4][4];
#pragma unroll
    for (int i = 0; i < 4; i++)
#pragma unroll
        for (int j = 0; j < 4; j++)
#pragma unroll
            for (int k = 0; k < 4; k++) acc[i][j][k] = 0.0f;

    const uint32_t a_row = (uint32_t)(wm * 64 + (lane & 15));
    const uint32_t a_chk = (uint32_t)(lane >> 4);
    const uint32_t b_row = (uint32_t)(wn * 32 + (lane & 7) + ((lane >> 4) << 3));
    const uint32_t b_chk = (uint32_t)((lane >> 3) & 1);

#pragma unroll
    for (int s = 0; s < BNS - 1; s++) {
        if (s < T) cpb_stage(sbase + s * BSTAGE_B, A, B, m0, n0, s * 64, K, tid);
        asm volatile("cp.async.commit_group;" ::: "memory");
    }

    for (int kt = 0; kt < T; kt++) {
        asm volatile("cp.async.wait_group %0;" :: "n"(BNS - 2) : "memory");
        __syncthreads();

        const int pre = kt + BNS - 1;
        if (pre < T)
            cpb_stage(sbase + (pre % BNS) * BSTAGE_B, A, B, m0, n0, pre * 64, K, tid);
        asm volatile("cp.async.commit_group;" ::: "memory");

        const uint32_t stA = sbase + (kt % BNS) * BSTAGE_B;
        const uint32_t stB = stA + BTILE_B;
#pragma unroll
        for (int ks = 0; ks < 4; ks++) {
            uint32_t bf[2][4];
            const uint32_t akc = (uint32_t)(ks * 2) + a_chk;
            const uint32_t bkc = (uint32_t)(ks * 2) + b_chk;
#pragma unroll
            for (int bi = 0; bi < 2; bi++) {
                uint32_t bo = BSW((b_row + bi * 16) * BP + bkc * 16);
                ldsm_x4(bf[bi], stB + bo);
            }
#pragma unroll
            for (int mi = 0; mi < 4; mi++) {
                uint32_t af[4];
                uint32_t ao = BSW((a_row + mi * 16) * BP + akc * 16);
                ldsm_x4(af, stA + ao);
#pragma unroll
                for (int ni = 0; ni < 4; ni++)
                    mma_bf16(acc[mi][ni], af, &bf[ni >> 1][(ni & 1) * 2]);
            }
        }
    }

    const int row0 = m0 + wm * 64 + (lane >> 2);
    const int col0 = n0 + wn * 32 + (lane & 3) * 2;
#pragma unroll
    for (int mi = 0; mi < 4; mi++) {
#pragma unroll
        for (int ni = 0; ni < 4; ni++) {
            int col = col0 + ni * 8;
            float bx = __ldg(bias + col), by = __ldg(bias + col + 1);
            float qs = ((flags & EPI_SCALEQ) && col < 512) ? 0.18033688f : 1.0f;
#pragma unroll
            for (int half = 0; half < 2; half++) {
                int r = row0 + mi * 16 + half * 8;
                float vx = acc[mi][ni][half * 2 + 0] + bx;
                float vy = acc[mi][ni][half * 2 + 1] + by;
                if (flags & EPI_GELU) { vx *= normcdff(vx); vy *= normcdff(vy); }
                vx *= qs; vy *= qs;
                if (Cb)
                    *(uint32_t*)(Cb + (size_t)r * N + col) = packbf2(vx, vy);
                else
                    *(float2*)(C + (size_t)r * N + col) = make_float2(vx, vy);
            }
        }
    }
}

// ====================== flash attention (bf16, PV lookahead) ===============
#define FPITCH 144
#define FTILE (64 * FPITCH)
#define FQTILE (128 * FPITCH)
#define FA_SMEM (FQTILE + 4 * FTILE)        // 55296 B

__device__ __forceinline__ void fa_cp(uint32_t dst, const __nv_bfloat16* src) {
    asm volatile("cp.async.cg.shared.global [%0], [%1], 16;" :: "r"(dst), "l"(src) : "memory");
}

__device__ __forceinline__ void fa_load_kv(uint32_t st, const __nv_bfloat16* qkv,
                                           size_t brow0, int t, int h, int tid)
{
#pragma unroll
    for (int i = 0; i < 2; i++) {
        int idx = tid + i * 256;
        int r = idx >> 3, c = idx & 7;
        uint32_t d = (uint32_t)(r * FPITCH + c * 16);
        size_t base = (brow0 + t + r) * (size_t)(3 * Dc) + h * HDc + c * 8;
        fa_cp(st + 0 * FTILE + d, qkv + base + Dc);
        fa_cp(st + 1 * FTILE + d, qkv + base + 2 * Dc);
    }
}

// exp2 + pack two S rows (8 values) into one A-fragment quad; accumulates l.
__device__ __forceinline__ void exp_pack(const float s0[4], const float s1[4],
                                         uint32_t ap[4], float& l0, float& l1)
{
    float e0 = ex2(s0[0]), e1 = ex2(s0[1]), e2 = ex2(s0[2]), e3 = ex2(s0[3]);
    l0 += e0 + e1; l1 += e2 + e3;
    ap[0] = packbf2(e0, e1);
    ap[1] = packbf2(e2, e3);
    float f0 = ex2(s1[0]), f1 = ex2(s1[1]), f2 = ex2(s1[2]), f3 = ex2(s1[3]);
    l0 += f0 + f1; l1 += f2 + f3;
    ap[2] = packbf2(f0, f1);
    ap[3] = packbf2(f2, f3);
}

__global__ __launch_bounds__(256, 2)
void flash_attn_mma_kernel(const __nv_bfloat16* __restrict__ qkv,
                           __nv_bfloat16* __restrict__ out)
{
    extern __shared__ char smem[];
    const uint32_t sb = smem_u32(smem);
    const uint32_t sQ = sb;
    const uint32_t sKV = sb + FQTILE;

    const int tid = threadIdx.x;
    const int wid = tid >> 5, lane = tid & 31;
    const int bh = blockIdx.y;
    const int b = bh >> 3, h = bh & 7;
    const int q0 = blockIdx.x << 7;
    const size_t brow0 = (size_t)b * Sc;

#pragma unroll
    for (int i = 0; i < 4; i++) {
        int idx = tid + i * 256;
        int r = idx >> 3, c = idx & 7;
        uint32_t d = (uint32_t)(r * FPITCH + c * 16);
        size_t base = (brow0 + q0 + r) * (size_t)(3 * Dc) + h * HDc + c * 8;
        fa_cp(sQ + d, qkv + base);
    }
    fa_load_kv(sKV, qkv, brow0, 0, h, tid);
    asm volatile("cp.async.commit_group;" ::: "memory");
    asm volatile("cp.async.wait_group 0;" ::: "memory");
    __syncthreads();

    const uint32_t a_row = (uint32_t)(wid * 16 + (lane & 15));
    const uint32_t a_chk = (uint32_t)(lane >> 4);
    const uint32_t b_row = (uint32_t)((lane & 7) + ((lane >> 4) << 3));
    const uint32_t b_chk = (uint32_t)((lane >> 3) & 1);
    const uint32_t v_row = (uint32_t)(lane & 15);
    const uint32_t v_col = (uint32_t)((lane >> 4) << 3);

    // hoist loop-invariant Q fragments
    uint32_t qreg[4][4];
#pragma unroll
    for (int ks = 0; ks < 4; ks++)
        ldsm_x4(qreg[ks], sQ + a_row * FPITCH + (a_chk + 2 * ks) * 16);

    float l0 = 0.0f, l1 = 0.0f;
    float o[8][4];
#pragma unroll
    for (int j = 0; j < 8; j++)
#pragma unroll
        for (int k = 0; k < 4; k++) o[j][k] = 0.0f;

    const int T = Sc / 64;
    for (int it = 0; it < T; it++) {
        const uint32_t cur = sKV + (uint32_t)(it & 1) * (2 * FTILE);
        if (it + 1 < T)
            fa_load_kv(sKV + (uint32_t)((it + 1) & 1) * (2 * FTILE),
                       qkv, brow0, (it + 1) * 64, h, tid);
        asm volatile("cp.async.commit_group;" ::: "memory");

        // ---- S' = Q' K^T ----
        float sacc[8][4];
#pragma unroll
        for (int j = 0; j < 8; j++)
#pragma unroll
            for (int k = 0; k < 4; k++) sacc[j][k] = 0.0f;

#pragma unroll
        for (int ks = 0; ks < 4; ks++) {
#pragma unroll
            for (int nt = 0; nt < 4; nt++) {
                uint32_t kf[4];
                uint32_t bo = (b_row + nt * 16) * FPITCH + (b_chk + 2 * ks) * 16;
                ldsm_x4(kf, cur + bo);
                mma_bf16(sacc[2 * nt],     qreg[ks], kf);
                mma_bf16(sacc[2 * nt + 1], qreg[ks], kf + 2);
            }
        }

        // ---- PV with exp lookahead-1: exp(ks+1) overlaps PV MMAs of ks ----
        uint32_t ap[4];
        exp_pack(sacc[0], sacc[1], ap, l0, l1);
#pragma unroll
        for (int ks = 0; ks < 4; ks++) {
            uint32_t apn[4];
            if (ks < 3)
                exp_pack(sacc[2 * ks + 2], sacc[2 * ks + 3], apn, l0, l1);
#pragma unroll
            for (int nt = 0; nt < 4; nt++) {
                uint32_t vf[4];
                uint32_t vo = (ks * 16 + v_row) * FPITCH + (nt * 16 + v_col) * 2;
                ldsm_x4_t(vf, cur + FTILE + vo);
                mma_bf16(o[2 * nt],     ap, vf);
                mma_bf16(o[2 * nt + 1], ap, vf + 2);
            }
            if (ks < 3) {
                ap[0] = apn[0]; ap[1] = apn[1];
                ap[2] = apn[2]; ap[3] = apn[3];
            }
        }

        if (it + 1 < T) asm volatile("cp.async.wait_group 0;" ::: "memory");
        __syncthreads();
    }

    l0 += __shfl_xor_sync(0xffffffffu, l0, 1);
    l0 += __shfl_xor_sync(0xffffffffu, l0, 2);
    l1 += __shfl_xor_sync(0xffffffffu, l1, 1);
    l1 += __shfl_xor_sync(0xffffffffu, l1, 2);

    const float inv0 = 1.0f / l0, inv1 = 1.0f / l1;
    const int r0 = (int)(brow0) + q0 + wid * 16 + (lane >> 2);
#pragma unroll
    for (int j = 0; j < 8; j++) {
        size_t col = (size_t)h * HDc + j * 8 + (lane & 3) * 2;
        *(uint32_t*)(out + (size_t)r0 * Dc + col) = packbf2(o[j][0] * inv0, o[j][1] * inv0);
        *(uint32_t*)(out + (size_t)(r0 + 8) * Dc + col) = packbf2(o[j][2] * inv1, o[j][3] * inv1);
    }
}

// =================== prep kernel (weights + x conversion, one launch) ======
__global__ __launch_bounds__(256)
void prep_kernel(const float* __restrict__ w_qkv, const float* __restrict__ w_o,
                 const float* __restrict__ w1, const float* __restrict__ w2,
                 const float* __restrict__ x,
                 __nv_bfloat16* __restrict__ Wb, __nv_bfloat16* __restrict__ xb)
{
    int id = blockIdx.x;
    if (id >= 3072) {
        int i = (id - 3072) * 256 + threadIdx.x;
        float4 v = ((const float4*)x)[i];
        ((uint32_t*)xb)[2 * i]     = packbf2(v.x, v.y);
        ((uint32_t*)xb)[2 * i + 1] = packbf2(v.z, v.w);
        return;
    }
    const float* W; int K, N, nx; size_t off;
    if (id < 768)        { W = w_qkv; K = Dc; N = 3 * Dc; nx = 48; off = OFF_WQKV; }
    else if (id < 1024)  { id -= 768;  W = w_o; K = Dc; N = Dc;    nx = 16; off = OFF_WO; }
    else if (id < 2048)  { id -= 1024; W = w1;  K = Dc; N = Fc;    nx = 64; off = OFF_W1; }
    else                 { id -= 2048; W = w2;  K = Fc; N = Dc;    nx = 16; off = OFF_W2; }
    const int n0 = (id % nx) * 32, k0 = (id / nx) * 32;

    __shared__ float tile[32][33];
    const int tx = threadIdx.x & 31, ty = threadIdx.x >> 5;
#pragma unroll
    for (int i = ty; i < 32; i += 8)
        tile[i][tx] = W[(size_t)(k0 + i) * N + n0 + tx];
    __syncthreads();
#pragma unroll
    for (int i = ty; i < 32; i += 8)
        Wb[off + (size_t)(n0 + i) * K + k0 + tx] = __float2bfloat16(tile[tx][i]);
}

// ======================= add + layernorm (2 rows per CTA) ==================
__global__ __launch_bounds__(256)
void add_ln_kernel(const float* __restrict__ a, const float* __restrict__ r,
                   const float* __restrict__ g, const float* __restrict__ be,
                   float* __restrict__ out, __nv_bfloat16* __restrict__ out_b)
{
    const int half = threadIdx.x >> 7;              // 0 or 1 -> row within pair
    const int row = blockIdx.x * 2 + half;
    const int tid = threadIdx.x & 127;
    const float4 a4 = ((const float4*)(a + (size_t)row * Dc))[tid];
    const float4 r4 = ((const float4*)(r + (size_t)row * Dc))[tid];
    float v0 = a4.x + r4.x, v1 = a4.y + r4.y, v2 = a4.z + r4.z, v3 = a4.w + r4.w;

    float s = v0 + v1 + v2 + v3;
    float q = v0 * v0 + v1 * v1 + v2 * v2 + v3 * v3;
#pragma unroll
    for (int o = 16; o > 0; o >>= 1) {
        s += __shfl_xor_sync(0xffffffffu, s, o);
        q += __shfl_xor_sync(0xffffffffu, q, o);
    }
    __shared__ float ss[2][4], sq[2][4];
    if ((tid & 31) == 0) { ss[half][tid >> 5] = s; sq[half][tid >> 5] = q; }
    __syncthreads();
    s = ss[half][0] + ss[half][1] + ss[half][2] + ss[half][3];
    q = sq[half][0] + sq[half][1] + sq[half][2] + sq[half][3];

    const float mu = s * (1.0f / Dc);
    const float var = q * (1.0f / Dc) - mu * mu;
    const float rstd = rsqrtf(var + 1e-5f);

    const float4 g4 = ((const float4*)g)[tid];
    const float4 b4 = ((const float4*)be)[tid];
    float4 ov;
    ov.x = (v0 - mu) * rstd * g4.x + b4.x;
    ov.y = (v1 - mu) * rstd * g4.y + b4.y;
    ov.z = (v2 - mu) * rstd * g4.z + b4.z;
    ov.w = (v3 - mu) * rstd * g4.w + b4.w;
    if (out) ((float4*)(out + (size_t)row * Dc))[tid] = ov;
    if (out_b) {
        uint32_t* bp = (uint32_t*)(out_b + (size_t)row * Dc) + 2 * tid;
        bp[0] = packbf2(ov.x, ov.y);
        bp[1] = packbf2(ov.z, ov.w);
    }
}

// ---------------------------------------------------------------------------
extern "C" void kernel_launch(void* const* d_in, const int* in_sizes, int n_in,
                              void* d_out, int out_size)
{
    (void)in_sizes; (void)n_in; (void)out_size;
    const float* x     = (const float*)d_in[0];
    const float* w_qkv = (const float*)d_in[1];
    const float* b_qkv = (const float*)d_in[2];
    const float* w_o   = (const float*)d_in[3];
    const float* b_o   = (const float*)d_in[4];
    const float* w1    = (const float*)d_in[5];
    const float* b1    = (const float*)d_in[6];
    const float* w2    = (const float*)d_in[7];
    const float* b2    = (const float*)d_in[8];
    const float* g1    = (const float*)d_in[9];
    const float* be1   = (const float*)d_in[10];
    const float* g2    = (const float*)d_in[11];
    const float* be2   = (const float*)d_in[12];

    float *proj, *ln1, *ffn;
    __nv_bfloat16 *xb, *qkv, *attnb, *ln1b, *hidb, *wb;
    cudaGetSymbolAddress((void**)&xb,    g_xb);
    cudaGetSymbolAddress((void**)&qkv,   g_qkv);
    cudaGetSymbolAddress((void**)&attnb, g_attnb);
    cudaGetSymbolAddress((void**)&proj,  g_proj);
    cudaGetSymbolAddress((void**)&ln1,   g_ln1);
    cudaGetSymbolAddress((void**)&ln1b,  g_ln1b);
    cudaGetSymbolAddress((void**)&hidb,  g_hidb);
    cudaGetSymbolAddress((void**)&ffn,   g_ffn);
    cudaGetSymbolAddress((void**)&wb,    g_wb);

    cudaFuncSetAttribute(gemm_bf16_kernel,
                         cudaFuncAttributeMaxDynamicSharedMemorySize, BGEMM_SMEM);
    cudaFuncSetAttribute(flash_attn_mma_kernel,
                         cudaFuncAttributeMaxDynamicSharedMemorySize, FA_SMEM);

    prep_kernel<<<3072 + 4096, 256>>>(w_qkv, w_o, w1, w2, x, wb, xb);

    gemm_bf16_kernel<<<dim3(12, 64), 256, BGEMM_SMEM>>>(xb, wb + OFF_WQKV, b_qkv,
                                                        nullptr, qkv, Dc, 3 * Dc, EPI_SCALEQ);
    flash_attn_mma_kernel<<<dim3(Sc / 128, Bc * Hc), 256, FA_SMEM>>>(qkv, attnb);
    gemm_bf16_kernel<<<dim3(4, 64), 256, BGEMM_SMEM>>>(attnb, wb + OFF_WO, b_o,
                                                       proj, nullptr, Dc, Dc, 0);
    add_ln_kernel<<<Mc / 2, 256>>>(proj, x, g1, be1, ln1, ln1b);
    gemm_bf16_kernel<<<dim3(16, 64), 256, BGEMM_SMEM>>>(ln1b, wb + OFF_W1, b1,
                                                        nullptr, hidb, Dc, Fc, EPI_GELU);
    gemm_bf16_kernel<<<dim3(4, 64), 256, BGEMM_SMEM>>>(hidb, wb + OFF_W2, b2,
                                                       ffn, nullptr, Fc, Dc, 0);
    add_ln_kernel<<<Mc / 2, 256>>>(ffn, ln1, g2, be2, (float*)d_out, nullptr);
}